// round 1
// baseline (speedup 1.0000x reference)
#include <cuda_runtime.h>
#include <cuda_bf16.h>
#include <math_constants.h>

// Problem constants
#define BATCH 64
#define SEQ   256
#define TCH   16
#define VOC   262
#define EMB   64
#define HID   32          // per direction; == warp size
#define G3    96          // 3*HID
#define NSEQ  (BATCH*SEQ) // 16384 words
#define NTASK (NSEQ*2)    // (seq, dir) tasks

// Scratch tables (device globals — no allocation allowed)
__device__ float g_GIf[VOC * G3];   // bih_f + Wih_f @ emb[c]
__device__ float g_GIb[VOC * G3];
__device__ float g_WhhTf[HID * G3]; // Whh transposed: [j][g]
__device__ float g_WhhTb[HID * G3];

__device__ __forceinline__ float sigf(float x) {
    // accurate-enough fast sigmoid: MUFU.EX2 + fast rcp, ~2ulp
    return __fdividef(1.0f, 1.0f + __expf(-x));
}
__device__ __forceinline__ float tanhfast(float x) {
    // tanh(x) = 2*sigmoid(2x) - 1
    return fmaf(2.0f, sigf(2.0f * x), -1.0f);
}

// ---------------------------------------------------------------------------
// Kernel 1: build GI tables (input-gate lookup per character) + transposed Whh
// grid = VOC+1 blocks, 96 threads each
// ---------------------------------------------------------------------------
__global__ void build_tables(const float* __restrict__ emb,
                             const float* __restrict__ Wih_f,
                             const float* __restrict__ bih_f,
                             const float* __restrict__ Wih_b,
                             const float* __restrict__ bih_b,
                             const float* __restrict__ Whh_f,
                             const float* __restrict__ Whh_b) {
    int c = blockIdx.x;
    int g = threadIdx.x;  // 0..95
    if (c < VOC) {
        __shared__ float e[EMB];
        if (g < EMB) e[g] = emb[c * EMB + g];
        __syncthreads();
        float af = bih_f[g];
        float ab = bih_b[g];
        #pragma unroll
        for (int k = 0; k < EMB; k++) {
            float ev = e[k];
            af = fmaf(Wih_f[g * EMB + k], ev, af);
            ab = fmaf(Wih_b[g * EMB + k], ev, ab);
        }
        g_GIf[c * G3 + g] = af;
        g_GIb[c * G3 + g] = ab;
    } else {
        // transpose Whh: WhhT[j*96 + g] = Whh[g*32 + j]
        for (int i = g; i < HID * G3; i += G3) {
            int gg = i / HID, j = i % HID;
            g_WhhTf[j * G3 + gg] = Whh_f[i];
            g_WhhTb[j * G3 + gg] = Whh_b[i];
        }
    }
}

// ---------------------------------------------------------------------------
// Kernel 2: persistent-warp bidirectional GRU + temporal max-pool.
// One warp handles one (sequence, direction) task; lane l owns h[l].
// Whh lives in 96 registers per lane, loaded once per warp (dir fixed by
// warp parity; grid-stride keeps parity since nwarps is even).
// ---------------------------------------------------------------------------
__global__ __launch_bounds__(256, 2)
void gru_main(const int* __restrict__ x,
              const float* __restrict__ bhh_f,
              const float* __restrict__ bhh_b,
              float* __restrict__ out) {
    int gtid   = blockIdx.x * blockDim.x + threadIdx.x;
    int w      = gtid >> 5;
    int lane   = gtid & 31;
    int nwarps = (gridDim.x * blockDim.x) >> 5;   // even by construction
    int dir    = w & 1;

    const float* __restrict__ GI  = dir ? g_GIb   : g_GIf;
    const float* __restrict__ WT  = dir ? g_WhhTb : g_WhhTf;
    const float* __restrict__ bhh = dir ? bhh_b   : bhh_f;

    // Per-lane recurrent weights: lane l needs rows {l, l+32, l+64} of Whh.
    float Wr[HID], Wz[HID], Wn[HID];
    #pragma unroll
    for (int j = 0; j < HID; j++) {
        Wr[j] = WT[j * G3 + lane];
        Wz[j] = WT[j * G3 + 32 + lane];
        Wn[j] = WT[j * G3 + 64 + lane];
    }
    float br = bhh[lane], bz = bhh[32 + lane], bn = bhh[64 + lane];

    for (int task = w; task < NTASK; task += nwarps) {
        int seq = task >> 1;   // task&1 == dir (parity preserved)

        // chars of this word live in lanes 0..15
        int cm = (lane < TCH) ? x[seq * TCH + lane] : 0;

        float h = 0.0f;
        float hmax = -CUDART_INF_F;

        #pragma unroll 1
        for (int tt = 0; tt < TCH; ++tt) {
            int t = dir ? (TCH - 1 - tt) : tt;
            int c = __shfl_sync(0xffffffffu, cm, t);

            const float* gp = GI + c * G3 + lane;
            float gir = gp[0];
            float giz = gp[32];
            float gin = gp[64];

            float ghr = br, ghz = bz, ghn = bn;
            #pragma unroll
            for (int j = 0; j < HID; j++) {
                float hj = __shfl_sync(0xffffffffu, h, j);
                ghr = fmaf(Wr[j], hj, ghr);
                ghz = fmaf(Wz[j], hj, ghz);
                ghn = fmaf(Wn[j], hj, ghn);
            }

            float r = sigf(gir + ghr);
            float z = sigf(giz + ghz);
            float n = tanhfast(fmaf(r, ghn, gin));
            h = fmaf(z, h - n, n);            // (1-z)*n + z*h
            hmax = fmaxf(hmax, h);
        }

        out[seq * (2 * HID) + dir * HID + lane] = hmax;
    }
}

// ---------------------------------------------------------------------------
// kernel_launch
// inputs (metadata order): x, emb, Wih_f, Whh_f, bih_f, bhh_f,
//                          Wih_b, Whh_b, bih_b, bhh_b
// output: float32 [64, 256, 64]
// ---------------------------------------------------------------------------
extern "C" void kernel_launch(void* const* d_in, const int* in_sizes, int n_in,
                              void* d_out, int out_size) {
    const int*   x     = (const int*)  d_in[0];
    const float* emb   = (const float*)d_in[1];
    const float* Wih_f = (const float*)d_in[2];
    const float* Whh_f = (const float*)d_in[3];
    const float* bih_f = (const float*)d_in[4];
    const float* bhh_f = (const float*)d_in[5];
    const float* Wih_b = (const float*)d_in[6];
    const float* Whh_b = (const float*)d_in[7];
    const float* bih_b = (const float*)d_in[8];
    const float* bhh_b = (const float*)d_in[9];
    float* out = (float*)d_out;

    build_tables<<<VOC + 1, G3>>>(emb, Wih_f, bih_f, Wih_b, bih_b, Whh_f, Whh_b);

    // 296 blocks x 256 threads = 2368 persistent warps (2 CTAs/SM at 128 regs)
    gru_main<<<296, 256>>>(x, bhh_f, bhh_b, out);
}